// round 17
// baseline (speedup 1.0000x reference)
#include <cuda_runtime.h>
#include <cuda_bf16.h>
#include <math.h>
#include <stdint.h>

#define B_ 4
#define T_ 1024
#define S_ 1024
#define E_ 1024
#define H_ 16
#define D_ 64
#define MAXLEN 2048

// ---------------- int8 split operands (15-bit fixed point per row) ----------
__device__ int8_t aqh_q[4096 * 1024], aql_q[4096 * 1024];
__device__ int8_t aqh_k[4096 * 1024], aql_k[4096 * 1024];
__device__ int8_t aqh_v[4096 * 1024], aql_v[4096 * 1024];
__device__ int8_t aqh_o[4096 * 1024], aql_o[4096 * 1024];   // quantized attention out
__device__ int8_t wqh_q[1024 * 1024], wql_q[1024 * 1024];
__device__ int8_t wqh_k[1024 * 1024], wql_k[1024 * 1024];
__device__ int8_t wqh_v[1024 * 1024], wql_v[1024 * 1024];
__device__ int8_t wqh_o[1024 * 1024], wql_o[1024 * 1024];
__device__ float scA_q[4096], scA_k[4096], scA_v[4096], scA_o[4096];
__device__ float scW_q[1024], scW_k[1024], scW_v[1024], scW_o[1024];

// Projected q/k/v for flash: [z][t][32] bf16 pair-words (pairs along d)
__device__ uint32_t gq_hi[64 * 1024 * 32], gq_lo[64 * 1024 * 32];
__device__ uint32_t gk_hi[64 * 1024 * 32], gk_lo[64 * 1024 * 32];
__device__ uint32_t gv_hi[64 * 1024 * 32], gv_lo[64 * 1024 * 32];
// Flash output (fp32), consumed by quant then proj_o
__device__ float g_ao_f[4096 * 1024];

__device__ __forceinline__ float neg_big() { return -1e30f; }

__device__ __forceinline__ void split2(float x, float y, uint32_t& hi, uint32_t& lo) {
    __nv_bfloat16 xh = __float2bfloat16(x);
    __nv_bfloat16 yh = __float2bfloat16(y);
    __nv_bfloat16 xl = __float2bfloat16(x - __bfloat162float(xh));
    __nv_bfloat16 yl = __float2bfloat16(y - __bfloat162float(yh));
    hi = (uint32_t)__bfloat16_as_ushort(xh) | ((uint32_t)__bfloat16_as_ushort(yh) << 16);
    lo = (uint32_t)__bfloat16_as_ushort(xl) | ((uint32_t)__bfloat16_as_ushort(yl) << 16);
}

__device__ __forceinline__ void mma_bf16(float c[4], const uint32_t a[4], const uint32_t b[2]) {
    asm volatile(
        "mma.sync.aligned.m16n8k16.row.col.f32.bf16.bf16.f32 "
        "{%0,%1,%2,%3}, {%4,%5,%6,%7}, {%8,%9}, {%0,%1,%2,%3};"
        : "+f"(c[0]), "+f"(c[1]), "+f"(c[2]), "+f"(c[3])
        : "r"(a[0]), "r"(a[1]), "r"(a[2]), "r"(a[3]), "r"(b[0]), "r"(b[1]));
}

__device__ __forceinline__ void mma_i8(int c[4], const uint32_t a[4], const uint32_t b[2]) {
    asm volatile(
        "mma.sync.aligned.m16n8k32.row.col.s32.s8.s8.s32 "
        "{%0,%1,%2,%3}, {%4,%5,%6,%7}, {%8,%9}, {%0,%1,%2,%3};"
        : "+r"(c[0]), "+r"(c[1]), "+r"(c[2]), "+r"(c[3])
        : "r"(a[0]), "r"(a[1]), "r"(a[2]), "r"(a[3]), "r"(b[0]), "r"(b[1]));
}

__device__ __forceinline__ uint32_t lds32(uint32_t a) {
    uint32_t r;
    asm volatile("ld.shared.b32 %0, [%1];" : "=r"(r) : "r"(a));
    return r;
}
__device__ __forceinline__ void ldmat_x2_trans(uint32_t& r0, uint32_t& r1, uint32_t addr) {
    asm volatile("ldmatrix.sync.aligned.m8n8.x2.trans.shared.b16 {%0,%1}, [%2];"
                 : "=r"(r0), "=r"(r1) : "r"(addr));
}
__device__ __forceinline__ void cpa16(uint32_t dst, const void* src) {
    asm volatile("cp.async.cg.shared.global [%0], [%1], 16;" :: "r"(dst), "l"(src));
}
template <int N>
__device__ __forceinline__ void cpa_wait() {
    asm volatile("cp.async.wait_group %0;" :: "n"(N) : "memory");
}
__device__ __forceinline__ void cpa_commit() {
    asm volatile("cp.async.commit_group;" ::: "memory");
}

// ---------------------------------------------------------------------------
// Row quantizer: one block per 1024-elem row. x = s*(256*ah + al), |q|<=32512.
// ---------------------------------------------------------------------------
__device__ __forceinline__ void quant_row(const float* src, int8_t* dh, int8_t* dl,
                                          float* sc, int row)
{
    __shared__ float red[8];
    const int tid = threadIdx.x;
    float4 xv = reinterpret_cast<const float4*>(src + (size_t)row * 1024)[tid];
    float mx = fmaxf(fmaxf(fabsf(xv.x), fabsf(xv.y)), fmaxf(fabsf(xv.z), fabsf(xv.w)));
#pragma unroll
    for (int o = 16; o; o >>= 1) mx = fmaxf(mx, __shfl_xor_sync(0xffffffffu, mx, o));
    if ((tid & 31) == 0) red[tid >> 5] = mx;
    __syncthreads();
    float m8 = red[0];
#pragma unroll
    for (int i = 1; i < 8; i++) m8 = fmaxf(m8, red[i]);
    float inv = (m8 > 0.0f) ? 32512.0f / m8 : 0.0f;
    if (tid == 0) sc[row] = (m8 > 0.0f) ? m8 / 32512.0f : 0.0f;

    const float e[4] = { xv.x, xv.y, xv.z, xv.w };
    char hq[4], lq[4];
#pragma unroll
    for (int c = 0; c < 4; c++) {
        int q = __float2int_rn(e[c] * inv);
        int ah = (q + 128) >> 8;
        int al = q - (ah << 8);
        hq[c] = (char)ah;
        lq[c] = (char)al;
    }
    reinterpret_cast<char4*>(dh + (size_t)row * 1024)[tid] = make_char4(hq[0], hq[1], hq[2], hq[3]);
    reinterpret_cast<char4*>(dl + (size_t)row * 1024)[tid] = make_char4(lq[0], lq[1], lq[2], lq[3]);
}

// Quantize all 7 inputs (3 activations + 4 weights). blockIdx.x = global row.
__global__ __launch_bounds__(256) void quant7(
    const float* __restrict__ q,  const float* __restrict__ k,
    const float* __restrict__ v,  const float* __restrict__ qw,
    const float* __restrict__ kw, const float* __restrict__ vw,
    const float* __restrict__ ow)
{
    int row = blockIdx.x;
    if (row < 12288) {
        int seg = row >> 12, lr = row & 4095;
        const float* src = (seg == 0) ? q : (seg == 1) ? k : v;
        int8_t* dh = (seg == 0) ? aqh_q : (seg == 1) ? aqh_k : aqh_v;
        int8_t* dl = (seg == 0) ? aql_q : (seg == 1) ? aql_k : aql_v;
        float* sc  = (seg == 0) ? scA_q : (seg == 1) ? scA_k : scA_v;
        quant_row(src, dh, dl, sc, lr);
    } else {
        int r2 = row - 12288;
        int seg = r2 >> 10, lr = r2 & 1023;
        const float* src = (seg == 0) ? qw : (seg == 1) ? kw : (seg == 2) ? vw : ow;
        int8_t* dh = (seg == 0) ? wqh_q : (seg == 1) ? wqh_k : (seg == 2) ? wqh_v : wqh_o;
        int8_t* dl = (seg == 0) ? wql_q : (seg == 1) ? wql_k : (seg == 2) ? wql_v : wql_o;
        float* sc  = (seg == 0) ? scW_q : (seg == 1) ? scW_k : (seg == 2) ? scW_v : scW_o;
        quant_row(src, dh, dl, sc, lr);
    }
}

// Quantize flash output rows
__global__ __launch_bounds__(256) void quant_ao()
{
    quant_row(g_ao_f, aqh_o, aql_o, scA_o, blockIdx.x);
}

// ---------------------------------------------------------------------------
// int8 GEMM mainloop. CTA tile 128x64, warp tile 64x16 (wy 2 x wx 4).
// Smem per stage 30720B: Ah @0 (128x80), Al @10240, Bh @20480 (64x80), Bl @25600.
// 2 stages = 61440B. K = 1024 in 16 k64 tiles, 2 k32 MMA steps each.
// Accumulators: ha (weight 65536) + ma (weight 256); al*bl dropped (zero-mean).
// ---------------------------------------------------------------------------
#define I8_BODY(AHp, ALp, BHp, BLp)                                               \
    const int lane = tid & 31, warp = tid >> 5;                                   \
    const int wy = warp >> 2, wx = warp & 3;                                      \
    const int grp = lane >> 2, tig = lane & 3;                                    \
    uint32_t sbase;                                                               \
    asm("{.reg .u64 t; cvta.to.shared.u64 t, %1; cvt.u32.u64 %0, t;}"             \
        : "=r"(sbase) : "l"(dsm));                                                \
    int ha[4][2][4], ma[4][2][4];                                                 \
    _Pragma("unroll")                                                             \
    for (int i = 0; i < 4; i++)                                                   \
        _Pragma("unroll")                                                         \
        for (int j = 0; j < 2; j++)                                               \
            _Pragma("unroll")                                                     \
            for (int r = 0; r < 4; r++) { ha[i][j][r] = 0; ma[i][j][r] = 0; }     \
    _Pragma("unroll")                                                             \
    for (int l = 0; l < 2; l++) {                                                 \
        int idx = tid + l * 256;                                                  \
        int row = idx >> 2, c4 = idx & 3;                                         \
        uint32_t off = (uint32_t)(row * 80 + c4 * 16);                            \
        size_t s = (size_t)(m0 + row) * 1024 + c4 * 16;                           \
        cpa16(sbase + off,         (AHp) + s);                                    \
        cpa16(sbase + 10240 + off, (ALp) + s);                                    \
    }                                                                             \
    {                                                                             \
        int row = tid >> 2, c4 = tid & 3;                                         \
        uint32_t off = (uint32_t)(row * 80 + c4 * 16);                            \
        size_t s = (size_t)(n0 + row) * 1024 + c4 * 16;                           \
        cpa16(sbase + 20480 + off, (BHp) + s);                                    \
        cpa16(sbase + 25600 + off, (BLp) + s);                                    \
    }                                                                             \
    cpa_commit();                                                                 \
    for (int t = 0; t < 16; t++) {                                                \
        const int st = t & 1;                                                     \
        if (t + 1 < 16) {                                                         \
            uint32_t so = (uint32_t)(st ^ 1) * 30720u;                            \
            _Pragma("unroll")                                                     \
            for (int l = 0; l < 2; l++) {                                         \
                int idx = tid + l * 256;                                          \
                int row = idx >> 2, c4 = idx & 3;                                 \
                uint32_t off = so + (uint32_t)(row * 80 + c4 * 16);               \
                size_t s = (size_t)(m0 + row) * 1024 + (t + 1) * 64 + c4 * 16;    \
                cpa16(sbase + off,         (AHp) + s);                            \
                cpa16(sbase + 10240 + off, (ALp) + s);                            \
            }                                                                     \
            {                                                                     \
                int row = tid >> 2, c4 = tid & 3;                                 \
                uint32_t off = so + (uint32_t)(row * 80 + c4 * 16);               \
                size_t s = (size_t)(n0 + row) * 1024 + (t + 1) * 64 + c4 * 16;    \
                cpa16(sbase + 20480 + off, (BHp) + s);                            \
                cpa16(sbase + 25600 + off, (BLp) + s);                            \
            }                                                                     \
            cpa_commit();                                                         \
            cpa_wait<1>();                                                        \
        } else {                                                                  \
            cpa_wait<0>();                                                        \
        }                                                                         \
        __syncthreads();                                                          \
        const uint32_t sb0 = sbase + st * 30720u;                                 \
        _Pragma("unroll")                                                         \
        for (int ks = 0; ks < 2; ks++) {                                          \
            const int kb = ks * 32;                                               \
            uint32_t bh[2][2], bl[2][2];                                          \
            _Pragma("unroll")                                                     \
            for (int j = 0; j < 2; j++) {                                         \
                uint32_t ba = sb0 + 20480 + (wx * 16 + j * 8 + grp) * 80 + kb + tig * 4; \
                bh[j][0] = lds32(ba);        bh[j][1] = lds32(ba + 16);           \
                bl[j][0] = lds32(ba + 5120); bl[j][1] = lds32(ba + 5136);         \
            }                                                                     \
            _Pragma("unroll")                                                     \
            for (int i = 0; i < 4; i++) {                                         \
                uint32_t aa = sb0 + (wy * 64 + i * 16 + grp) * 80 + kb + tig * 4; \
                uint32_t ah[4] = { lds32(aa), lds32(aa + 640),                    \
                                   lds32(aa + 16), lds32(aa + 656) };             \
                uint32_t al[4] = { lds32(aa + 10240), lds32(aa + 10880),          \
                                   lds32(aa + 10256), lds32(aa + 10896) };        \
                _Pragma("unroll")                                                 \
                for (int j = 0; j < 2; j++) mma_i8(ha[i][j], ah, bh[j]);          \
                _Pragma("unroll")                                                 \
                for (int j = 0; j < 2; j++) mma_i8(ma[i][j], ah, bl[j]);          \
                _Pragma("unroll")                                                 \
                for (int j = 0; j < 2; j++) mma_i8(ma[i][j], al, bh[j]);          \
            }                                                                     \
        }                                                                         \
        __syncthreads();                                                          \
    }

// ---------------------------------------------------------------------------
// Merged Q/K/V projection (int8): blockIdx.z selects projection.
// Grid (1024/64, 4096/128, 3).
// ---------------------------------------------------------------------------
__global__ __launch_bounds__(256, 2) void proj_qkv_i8(
    const float* __restrict__ q_b, const float* __restrict__ k_b,
    const float* __restrict__ v_b, const float* __restrict__ rel)
{
    extern __shared__ uint32_t dsm[];
    const int which = blockIdx.z;
    const int tid = threadIdx.x;
    const int m0 = blockIdx.y * 128;
    const int n0 = blockIdx.x * 64;

    const int8_t* AHp = (which == 0) ? aqh_q : (which == 1) ? aqh_k : aqh_v;
    const int8_t* ALp = (which == 0) ? aql_q : (which == 1) ? aql_k : aql_v;
    const int8_t* BHp = (which == 0) ? wqh_q : (which == 1) ? wqh_k : wqh_v;
    const int8_t* BLp = (which == 0) ? wql_q : (which == 1) ? wql_k : wql_v;
    const float* SAs  = (which == 0) ? scA_q : (which == 1) ? scA_k : scA_v;
    const float* SBs  = (which == 0) ? scW_q : (which == 1) ? scW_k : scW_v;
    const float* bias = (which == 0) ? q_b : (which == 1) ? k_b : v_b;
    uint32_t* Dh = (which == 0) ? gq_hi : (which == 1) ? gk_hi : gv_hi;
    uint32_t* Dl = (which == 0) ? gq_lo : (which == 1) ? gk_lo : gv_lo;

    I8_BODY(AHp, ALp, BHp, BLp)

#pragma unroll
    for (int i = 0; i < 4; i++) {
        int mrow = m0 + wy * 64 + i * 16 + grp;
#pragma unroll
        for (int j = 0; j < 2; j++) {
            int ne = n0 + wx * 16 + j * 8 + 2 * tig;
            int h = ne >> 6, dl = ne & 63, dw = dl >> 1;
            float sb0v = SBs[ne], sb1v = SBs[ne + 1];
            float b0 = bias[ne], b1 = bias[ne + 1];
#pragma unroll
            for (int half = 0; half < 2; half++) {
                int m = mrow + half * 8;
                int bb = m >> 10, tt = m & 1023;
                float sa = SAs[m];
                float v0 = sa * sb0v * (65536.0f * (float)ha[i][j][2 * half]
                                        + 256.0f * (float)ma[i][j][2 * half]) + b0;
                float v1 = sa * sb1v * (65536.0f * (float)ha[i][j][2 * half + 1]
                                        + 256.0f * (float)ma[i][j][2 * half + 1]) + b1;
                if (which == 1) {
                    v0 += rel[((size_t)h * MAXLEN + tt) * D_ + dl];
                    v1 += rel[((size_t)h * MAXLEN + tt) * D_ + dl + 1];
                }
                uint32_t hw, lw;
                split2(v0, v1, hw, lw);
                size_t di = ((size_t)(bb * H_ + h) * T_ + tt) * 32 + dw;
                Dh[di] = hw;
                Dl[di] = lw;
            }
        }
    }
}

// ---------------------------------------------------------------------------
// O projection (int8): quantized ao @ ow^T + bias -> fp32 out. Grid (16, 32).
// ---------------------------------------------------------------------------
__global__ __launch_bounds__(256, 2) void proj_o_i8(
    const float* __restrict__ bias, float* __restrict__ out)
{
    extern __shared__ uint32_t dsm[];
    const int tid = threadIdx.x;
    const int m0 = blockIdx.y * 128;
    const int n0 = blockIdx.x * 64;

    I8_BODY(aqh_o, aql_o, wqh_o, wql_o)

#pragma unroll
    for (int i = 0; i < 4; i++) {
        int mrow = m0 + wy * 64 + i * 16 + grp;
#pragma unroll
        for (int j = 0; j < 2; j++) {
            int ne = n0 + wx * 16 + j * 8 + 2 * tig;
            float sb0v = scW_o[ne], sb1v = scW_o[ne + 1];
            float b0 = bias[ne], b1 = bias[ne + 1];
#pragma unroll
            for (int half = 0; half < 2; half++) {
                int m = mrow + half * 8;
                float sa = scA_o[m];
                out[(size_t)m * E_ + ne] = sa * sb0v *
                    (65536.0f * (float)ha[i][j][2 * half] + 256.0f * (float)ma[i][j][2 * half]) + b0;
                out[(size_t)m * E_ + ne + 1] = sa * sb1v *
                    (65536.0f * (float)ha[i][j][2 * half + 1] + 256.0f * (float)ma[i][j][2 * half + 1]) + b1;
            }
        }
    }
}

// ---------------------------------------------------------------------------
// Fused flash attention (R11 proven core); epilogue writes fp32 g_ao_f.
// ---------------------------------------------------------------------------
__global__ __launch_bounds__(256, 2) void flash_attn(const unsigned char* __restrict__ mask)
{
    extern __shared__ uint32_t sm[];
    uint32_t* Qhi = sm;
    uint32_t* Qlo = sm + 4608;

    const int tid = threadIdx.x;
    const int lane = tid & 31, warp = tid >> 5;
    const int grp = lane >> 2, tig = lane & 3;
    const int m0 = blockIdx.x * 128;
    const int z  = blockIdx.y;
    const int bb = z >> 4, h = z & 15;

    const unsigned char* mrow_g = mask + (size_t)bb * S_;

    uint32_t sbase;
    asm("{.reg .u64 t; cvta.to.shared.u64 t, %1; cvt.u32.u64 %0, t;}"
        : "=r"(sbase) : "l"(sm));
    const uint32_t vrow0 = sbase + 55296 + (lane & 15) * 144;

#pragma unroll
    for (int l = 0; l < 4; l++) {
        int idx = tid + l * 256;
        int row = idx >> 3, c4 = idx & 7;
        uint32_t off = (uint32_t)(row * 144 + c4 * 16);
        size_t src = ((size_t)z * T_ + m0 + row) * 32 + c4 * 4;
        cpa16(sbase + off,         gq_hi + src);
        cpa16(sbase + 18432 + off, gq_lo + src);
    }

#define KVFILL(tt, sg)                                                            \
    {                                                                             \
        uint32_t sgo = (uint32_t)(sg) * 36864;                                    \
        _Pragma("unroll")                                                         \
        for (int l = 0; l < 2; l++) {                                             \
            int idx = tid + l * 256;                                              \
            int row = idx >> 3, c4 = idx & 7;                                     \
            uint32_t off = sgo + (uint32_t)(row * 144 + c4 * 16);                 \
            size_t src = ((size_t)z * S_ + (tt) * 64 + row) * 32 + c4 * 4;        \
            cpa16(sbase + 36864 + off, gk_hi + src);                              \
            cpa16(sbase + 46080 + off, gk_lo + src);                              \
            cpa16(sbase + 55296 + off, gv_hi + src);                              \
            cpa16(sbase + 64512 + off, gv_lo + src);                              \
        }                                                                         \
        cpa_commit();                                                             \
    }

    float accO[8][4];
#pragma unroll
    for (int jd = 0; jd < 8; jd++)
#pragma unroll
        for (int r = 0; r < 4; r++) accO[jd][r] = 0.0f;
    float m0r = -1e29f, m1r = -1e29f, l0r = 0.0f, l1r = 0.0f;

    const int r0 = warp * 16 + grp;

    KVFILL(0, 0);

    for (int t = 0; t < S_ / 64; t++) {
        const int st = t & 1;
        const int s0 = t * 64;
        if (t + 1 < S_ / 64) { KVFILL(t + 1, st ^ 1); cpa_wait<1>(); }
        else                 { cpa_wait<0>(); }
        __syncthreads();

        const uint32_t* KhiS = sm + 9216 + st * 9216;
        const uint32_t* KloS = sm + 11520 + st * 9216;
        const uint32_t vrow_h = vrow0 + st * 36864;

        float acc[8][4];
#pragma unroll
        for (int j = 0; j < 8; j++)
#pragma unroll
            for (int r = 0; r < 4; r++) acc[j][r] = 0.0f;

#pragma unroll
        for (int ks = 0; ks < 4; ks++) {
            const int kb = ks * 8;
            uint32_t qh[4], ql[4];
            qh[0] = Qhi[r0 * 36 + kb + tig];
            qh[1] = Qhi[(r0 + 8) * 36 + kb + tig];
            qh[2] = Qhi[r0 * 36 + kb + tig + 4];
            qh[3] = Qhi[(r0 + 8) * 36 + kb + tig + 4];
            ql[0] = Qlo[r0 * 36 + kb + tig];
            ql[1] = Qlo[(r0 + 8) * 36 + kb + tig];
            ql[2] = Qlo[r0 * 36 + kb + tig + 4];
            ql[3] = Qlo[(r0 + 8) * 36 + kb + tig + 4];
#pragma unroll
            for (int j = 0; j < 8; j++) {
                int c0 = j * 8 + grp;
                uint32_t kh[2], kl[2];
                kh[0] = KhiS[c0 * 36 + kb + tig];
                kh[1] = KhiS[c0 * 36 + kb + tig + 4];
                kl[0] = KloS[c0 * 36 + kb + tig];
                kl[1] = KloS[c0 * 36 + kb + tig + 4];
                mma_bf16(acc[j], qh, kh);
                mma_bf16(acc[j], ql, kh);
                mma_bf16(acc[j], qh, kl);
            }
        }

#pragma unroll
        for (int j = 0; j < 8; j++) {
            int c = s0 + j * 8 + 2 * tig;
            if (mrow_g[c])     { acc[j][0] = neg_big(); acc[j][2] = neg_big(); }
            if (mrow_g[c + 1]) { acc[j][1] = neg_big(); acc[j][3] = neg_big(); }
        }

        float tm0 = neg_big(), tm1 = neg_big();
#pragma unroll
        for (int j = 0; j < 8; j++) {
            tm0 = fmaxf(tm0, fmaxf(acc[j][0], acc[j][1]));
            tm1 = fmaxf(tm1, fmaxf(acc[j][2], acc[j][3]));
        }
        tm0 = fmaxf(tm0, __shfl_xor_sync(0xffffffffu, tm0, 1));
        tm0 = fmaxf(tm0, __shfl_xor_sync(0xffffffffu, tm0, 2));
        tm1 = fmaxf(tm1, __shfl_xor_sync(0xffffffffu, tm1, 1));
        tm1 = fmaxf(tm1, __shfl_xor_sync(0xffffffffu, tm1, 2));

        float mn0 = fmaxf(fmaxf(m0r, tm0), -1e29f);
        float mn1 = fmaxf(fmaxf(m1r, tm1), -1e29f);
        float sc0 = __expf(m0r - mn0);
        float sc1 = __expf(m1r - mn1);

        float ts0 = 0.0f, ts1 = 0.0f;
#pragma unroll
        for (int j = 0; j < 8; j++) {
            acc[j][0] = __expf(acc[j][0] - mn0);
            acc[j][1] = __expf(acc[j][1] - mn0);
            acc[j][2] = __expf(acc[j][2] - mn1);
            acc[j][3] = __expf(acc[j][3] - mn1);
            ts0 += acc[j][0] + acc[j][1];
            ts1 += acc[j][2] + acc[j][3];
        }
        ts0 += __shfl_xor_sync(0xffffffffu, ts0, 1);
        ts0 += __shfl_xor_sync(0xffffffffu, ts0, 2);
        ts1 += __shfl_xor_sync(0xffffffffu, ts1, 1);
        ts1 += __shfl_xor_sync(0xffffffffu, ts1, 2);

        l0r = l0r * sc0 + ts0;
        l1r = l1r * sc1 + ts1;
        m0r = mn0; m1r = mn1;

#pragma unroll
        for (int jd = 0; jd < 8; jd++) {
            accO[jd][0] *= sc0; accO[jd][1] *= sc0;
            accO[jd][2] *= sc1; accO[jd][3] *= sc1;
        }

#pragma unroll
        for (int ks = 0; ks < 4; ks++) {
            uint32_t ah[4], al[4];
            split2(acc[2 * ks][0],     acc[2 * ks][1],     ah[0], al[0]);
            split2(acc[2 * ks][2],     acc[2 * ks][3],     ah[1], al[1]);
            split2(acc[2 * ks + 1][0], acc[2 * ks + 1][1], ah[2], al[2]);
            split2(acc[2 * ks + 1][2], acc[2 * ks + 1][3], ah[3], al[3]);
            uint32_t rbase = vrow_h + ks * 2304;
#pragma unroll
            for (int jd = 0; jd < 8; jd++) {
                uint32_t bh[2], bl[2];
                ldmat_x2_trans(bh[0], bh[1], rbase + jd * 16);
                ldmat_x2_trans(bl[0], bl[1], rbase + jd * 16 + 9216);
                mma_bf16(accO[jd], ah, bh);
                mma_bf16(accO[jd], al, bh);
                mma_bf16(accO[jd], ah, bl);
            }
        }
        __syncthreads();
    }
#undef KVFILL

    // Epilogue: normalized O -> fp32 g_ao_f [4096][1024]
    float inv0 = 1.0f / l0r, inv1 = 1.0f / l1r;
    size_t row0 = (size_t)bb * T_ + m0 + warp * 16 + grp;
    size_t row1 = row0 + 8;
#pragma unroll
    for (int jd = 0; jd < 8; jd++) {
        int d = h * 64 + jd * 8 + 2 * tig;
        g_ao_f[row0 * 1024 + d]     = accO[jd][0] * inv0;
        g_ao_f[row0 * 1024 + d + 1] = accO[jd][1] * inv0;
        g_ao_f[row1 * 1024 + d]     = accO[jd][2] * inv1;
        g_ao_f[row1 * 1024 + d + 1] = accO[jd][3] * inv1;
    }
}

extern "C" void kernel_launch(void* const* d_in, const int* in_sizes, int n_in,
                              void* d_out, int out_size)
{
    const float* query = (const float*)d_in[0];
    const float* key   = (const float*)d_in[1];
    const float* value = (const float*)d_in[2];
    const unsigned char* mask = (const unsigned char*)d_in[3];
    const float* q_w = (const float*)d_in[4];
    const float* q_b = (const float*)d_in[5];
    const float* k_w = (const float*)d_in[6];
    const float* k_b = (const float*)d_in[7];
    const float* v_w = (const float*)d_in[8];
    const float* v_b = (const float*)d_in[9];
    const float* o_w = (const float*)d_in[10];
    const float* o_b = (const float*)d_in[11];
    const float* rel = (const float*)d_in[12];
    float* out = (float*)d_out;

    const int ISMEM = 61440;
    const int FSMEM = 110592;
    cudaFuncSetAttribute(proj_qkv_i8, cudaFuncAttributeMaxDynamicSharedMemorySize, ISMEM);
    cudaFuncSetAttribute(proj_o_i8,   cudaFuncAttributeMaxDynamicSharedMemorySize, ISMEM);
    cudaFuncSetAttribute(flash_attn,  cudaFuncAttributeMaxDynamicSharedMemorySize, FSMEM);

    // Quantize 3 activations + 4 weight matrices (16384 rows)
    quant7<<<16384, 256>>>(query, key, value, q_w, k_w, v_w, o_w);

    // Q/K/V projections (int8)
    dim3 pg(E_ / 64, (B_ * T_) / 128, 3);
    proj_qkv_i8<<<pg, 256, ISMEM>>>(q_b, k_b, v_b, rel);

    // Fused attention (bf16x3)
    dim3 fg(T_ / 128, B_ * H_, 1);
    flash_attn<<<fg, 256, FSMEM>>>(mask);

    // Quantize attention output rows, then O projection (int8)
    quant_ao<<<4096, 256>>>();
    dim3 og(E_ / 64, (B_ * T_) / 128, 1);
    proj_o_i8<<<og, 256, ISMEM>>>(o_b, out);
}